// round 11
// baseline (speedup 1.0000x reference)
#include <cuda_runtime.h>
#include <cuda_fp16.h>
#include <cstdint>

#define T_TOK   8192
#define DMODEL  1024
#define DFF     4096
#define NEXP    8
#define MAX_SLOTS 17408          // 16384 assignments + per-expert pad to 128
#define MAX_TILES 136            // MAX_SLOTS / 128
#define KC 32                    // k per chunk
#define SW 20                    // words (uint32) per plane row; 20g+tg covers all banks
#define PLANE_W (128 * SW)       // 2560 words per plane
#define AH_OFF 0
#define AL_OFF PLANE_W
#define BH_OFF (2 * PLANE_W)
#define BL_OFF (3 * PLANE_W)
#define STAGE_W (4 * PLANE_W)    // 10240 words = 40960 B
#define NSTAGE 2
#define NTHR 128                 // 4 warps per CTA, 2 CTAs/SM
#define SMEM_BYTES (NSTAGE * STAGE_W * 4)   // 81920 B

// ---------------- device scratch (no allocation allowed) ----------------
__device__ __half g_xh [(size_t)T_TOK * DMODEL];
__device__ __half g_xl [(size_t)T_TOK * DMODEL];
__device__ __half g_w1h[(size_t)NEXP * DFF * DMODEL];   // [e][n=DFF][k=DMODEL]
__device__ __half g_w1l[(size_t)NEXP * DFF * DMODEL];
__device__ __half g_w2h[(size_t)NEXP * DMODEL * DFF];   // [e][n=DMODEL][k=DFF]
__device__ __half g_w2l[(size_t)NEXP * DMODEL * DFF];
__device__ __half g_hh [(size_t)MAX_SLOTS * DFF];
__device__ __half g_hl [(size_t)MAX_SLOTS * DFF];
__device__ int   g_slot_token[MAX_SLOTS];
__device__ float g_slot_gate[MAX_SLOTS];
__device__ int   g_counts[NEXP];
__device__ int   g_fill[NEXP];
__device__ int   g_offsets[NEXP];
__device__ int   g_tile_expert[MAX_TILES];
__device__ int   g_tok_expert[T_TOK * 2];
__device__ float g_tok_gate[T_TOK * 2];

// ---------------- helpers ----------------
__device__ __forceinline__ void mma_f16(float c[4], const uint32_t a[4], const uint32_t b[2]) {
    asm volatile(
        "mma.sync.aligned.m16n8k16.row.col.f32.f16.f16.f32 "
        "{%0,%1,%2,%3}, {%4,%5,%6,%7}, {%8,%9}, {%0,%1,%2,%3};\n"
        : "+f"(c[0]), "+f"(c[1]), "+f"(c[2]), "+f"(c[3])
        : "r"(a[0]), "r"(a[1]), "r"(a[2]), "r"(a[3]), "r"(b[0]), "r"(b[1]));
}
__device__ __forceinline__ void cp16(uint32_t smem_addr, const void* gmem, int src_bytes) {
    asm volatile("cp.async.cg.shared.global [%0], [%1], 16, %2;\n"
                 :: "r"(smem_addr), "l"(gmem), "r"(src_bytes));
}
__device__ __forceinline__ void cp_commit() {
    asm volatile("cp.async.commit_group;\n" ::: "memory");
}
__device__ __forceinline__ void cp_wait1() {
    asm volatile("cp.async.wait_group 1;\n" ::: "memory");
}

// ---------------- 0: reset ----------------
__global__ void reset_kernel() {
    int i = blockIdx.x * 256 + threadIdx.x;
    if (i < MAX_SLOTS) g_slot_token[i] = -1;
    if (i < NEXP) { g_counts[i] = 0; g_fill[i] = 0; }
}

// ---------------- 0b: split x into fp16 hi/lo planes ----------------
__global__ __launch_bounds__(256) void split_x_kernel(const float4* __restrict__ x) {
    size_t i = (size_t)blockIdx.x * 256 + threadIdx.x;
    float4 v = x[i];
    __half h0 = __float2half_rn(v.x), h1 = __float2half_rn(v.y);
    __half h2 = __float2half_rn(v.z), h3 = __float2half_rn(v.w);
    __half l0 = __float2half_rn(v.x - __half2float(h0));
    __half l1 = __float2half_rn(v.y - __half2float(h1));
    __half l2 = __float2half_rn(v.z - __half2float(h2));
    __half l3 = __float2half_rn(v.w - __half2float(h3));
    __half2* oh = (__half2*)(g_xh + 4 * i);
    __half2* ol = (__half2*)(g_xl + 4 * i);
    oh[0] = __halves2half2(h0, h1); oh[1] = __halves2half2(h2, h3);
    ol[0] = __halves2half2(l0, l1); ol[1] = __halves2half2(l2, l3);
}

// ---------------- 0c: transpose + split weights: [e][K][N] f32 -> [e][N][K] half hi/lo ----------------
__global__ __launch_bounds__(256) void split_w_kernel(
    const float* __restrict__ src, __half* __restrict__ dh, __half* __restrict__ dl,
    int K, int N)
{
    __shared__ float tile[32][33];
    int e = blockIdx.z;
    const float* s = src + (size_t)e * K * N;
    __half* oh = dh + (size_t)e * K * N;
    __half* ol = dl + (size_t)e * K * N;
    int n0 = blockIdx.x * 32, k0 = blockIdx.y * 32;
    int tx = threadIdx.x, ty = threadIdx.y;   // 32 x 8
    #pragma unroll
    for (int j = 0; j < 32; j += 8)
        tile[ty + j][tx] = s[(size_t)(k0 + ty + j) * N + n0 + tx];
    __syncthreads();
    #pragma unroll
    for (int j = 0; j < 32; j += 8) {
        float v = tile[tx][ty + j];
        int n = n0 + ty + j;
        __half hh = __float2half_rn(v);
        __half hl = __float2half_rn(v - __half2float(hh));
        oh[(size_t)n * K + k0 + tx] = hh;
        ol[(size_t)n * K + k0 + tx] = hl;
    }
}

// ---------------- 1: router (one warp per token) ----------------
__global__ __launch_bounds__(256) void router_kernel(
    const float* __restrict__ x, const float* __restrict__ noise_u,
    const float* __restrict__ wg, const float* __restrict__ bg,
    const float* __restrict__ wn, const float* __restrict__ bn)
{
    __shared__ float sW[512][20];
    const int tid = threadIdx.x;
    const int wid = tid >> 5, lane = tid & 31;
    const int t = blockIdx.x * 8 + wid;

    float acc[16];
    #pragma unroll
    for (int j = 0; j < 16; j++) acc[j] = 0.f;

    for (int c = 0; c < 2; c++) {
        #pragma unroll
        for (int it = 0; it < 8; it++) {
            int idx = it * 256 + tid;
            int row = idx >> 2, qq = idx & 3;
            int grow = c * 512 + row;
            float4 v;
            if (qq < 2) v = *(const float4*)(wg + (size_t)grow * NEXP + qq * 4);
            else        v = *(const float4*)(wn + (size_t)grow * NEXP + (qq - 2) * 4);
            *(float4*)&sW[row][qq * 4] = v;
        }
        __syncthreads();

        const float* xr = x + (size_t)t * DMODEL + c * 512;
        for (int kk = lane; kk < 512; kk += 32) {
            float xv = xr[kk];
            float4 a0 = *(const float4*)&sW[kk][0];
            float4 a1 = *(const float4*)&sW[kk][4];
            float4 b0 = *(const float4*)&sW[kk][8];
            float4 b1 = *(const float4*)&sW[kk][12];
            acc[0]  += xv * a0.x; acc[1]  += xv * a0.y; acc[2]  += xv * a0.z; acc[3]  += xv * a0.w;
            acc[4]  += xv * a1.x; acc[5]  += xv * a1.y; acc[6]  += xv * a1.z; acc[7]  += xv * a1.w;
            acc[8]  += xv * b0.x; acc[9]  += xv * b0.y; acc[10] += xv * b0.z; acc[11] += xv * b0.w;
            acc[12] += xv * b1.x; acc[13] += xv * b1.y; acc[14] += xv * b1.z; acc[15] += xv * b1.w;
        }
        __syncthreads();
    }

    #pragma unroll
    for (int j = 0; j < 16; j++) {
        float v = acc[j];
        #pragma unroll
        for (int o = 16; o > 0; o >>= 1) v += __shfl_xor_sync(0xffffffffu, v, o);
        acc[j] = v;
    }

    if (lane == 0) {
        float v0 = -1e30f, v1 = -1e30f;
        int i0 = 0, i1 = 0;
        #pragma unroll
        for (int e = 0; e < NEXP; e++) {
            float lg = acc[e] + bg[e];
            float nl = acc[8 + e] + bn[e];
            float sp = fmaxf(nl, 0.f) + log1pf(expf(-fabsf(nl)));
            float nz = lg + noise_u[(size_t)t * NEXP + e] * sp;
            if (nz > v0)      { v1 = v0; i1 = i0; v0 = nz; i0 = e; }
            else if (nz > v1) { v1 = nz; i1 = e; }
        }
        float e1 = expf(v1 - v0);
        float s  = 1.f + e1;
        int o = t * 2;
        g_tok_expert[o]     = i0; g_tok_gate[o]     = 1.f / s;
        g_tok_expert[o + 1] = i1; g_tok_gate[o + 1] = e1 / s;
        atomicAdd(&g_counts[i0], 1);
        atomicAdd(&g_counts[i1], 1);
    }
}

// ---------------- 2: offsets ----------------
__global__ void offsets_kernel() {
    if (threadIdx.x == 0 && blockIdx.x == 0) {
        int off = 0;
        for (int e = 0; e < NEXP; e++) {
            g_offsets[e] = off;
            int tiles = (g_counts[e] + 127) >> 7;
            for (int i = 0; i < tiles; i++) g_tile_expert[(off >> 7) + i] = e;
            off += tiles << 7;
        }
        for (int i = off >> 7; i < MAX_TILES; i++) g_tile_expert[i] = -1;
    }
}

// ---------------- 3: scatter ----------------
__global__ void scatter_kernel() {
    int i = blockIdx.x * 256 + threadIdx.x;
    if (i >= T_TOK * 2) return;
    int e = g_tok_expert[i];
    float gt = g_tok_gate[i];
    int pos = atomicAdd(&g_fill[e], 1);
    int slot = g_offsets[e] + pos;
    g_slot_token[slot] = i >> 1;
    g_slot_gate[slot]  = gt;
}

// ---------------- 4: zero output ----------------
__global__ void zero_out_kernel(float4* __restrict__ out) {
    out[(size_t)blockIdx.x * 256 + threadIdx.x] = make_float4(0.f, 0.f, 0.f, 0.f);
}

// ================= fp16-split GEMM core: 4 warps (2m x 2n), 64x64 warp tiles =================
// Stage layout (uint32 words): Ah[128][SW], Al[128][SW], Bh[128][SW], Bl[128][SW].
// A rows = m (k contiguous), B rows = n (k contiguous). 3 MMAs per (mt,nt,k16):
// acc += Ah*Bh + Ah*Bl + Al*Bh  (lo*lo dropped, ~2^-22).
__device__ __forceinline__ void compute_chunk(
    const uint32_t* __restrict__ S, int wm, int wn, int g, int tg, float acc[4][8][4])
{
    #pragma unroll
    for (int step = 0; step < 2; step++) {
        const int kw = step * 8 + tg;
        uint32_t ah[4][4], al[4][4], bh[8][2], bl[8][2];
        #pragma unroll
        for (int mt = 0; mt < 4; mt++) {
            int base = (wm * 64 + mt * 16 + g) * SW + kw;
            ah[mt][0] = S[AH_OFF + base];
            ah[mt][1] = S[AH_OFF + base + 8 * SW];
            ah[mt][2] = S[AH_OFF + base + 4];
            ah[mt][3] = S[AH_OFF + base + 8 * SW + 4];
            al[mt][0] = S[AL_OFF + base];
            al[mt][1] = S[AL_OFF + base + 8 * SW];
            al[mt][2] = S[AL_OFF + base + 4];
            al[mt][3] = S[AL_OFF + base + 8 * SW + 4];
        }
        #pragma unroll
        for (int nt = 0; nt < 8; nt++) {
            int base = (wn * 64 + nt * 8 + g) * SW + kw;
            bh[nt][0] = S[BH_OFF + base];
            bh[nt][1] = S[BH_OFF + base + 4];
            bl[nt][0] = S[BL_OFF + base];
            bl[nt][1] = S[BL_OFF + base + 4];
        }
        #pragma unroll
        for (int mt = 0; mt < 4; mt++)
            #pragma unroll
            for (int nt = 0; nt < 8; nt++) {
                mma_f16(acc[mt][nt], ah[mt], bh[nt]);
                mma_f16(acc[mt][nt], ah[mt], bl[nt]);
                mma_f16(acc[mt][nt], al[mt], bh[nt]);
            }
    }
}

// ---------------- 5: gemm1  h = split(relu(gather(X) @ w1[e] + b1)) ----------------
__global__ __launch_bounds__(NTHR, 2) void gemm1_kernel(const float* __restrict__ b1)
{
    const int tile = blockIdx.y;
    const int e = g_tile_expert[tile];
    if (e < 0) return;
    const int n0 = blockIdx.x * 128;
    const int base = tile * 128;

    extern __shared__ uint32_t smem[];
    __shared__ int sTok[128];

    const int tid = threadIdx.x;
    sTok[tid] = g_slot_token[base + tid];
    __syncthreads();

    const uint32_t smem_u32 = (uint32_t)__cvta_generic_to_shared(smem);

    // fetch descriptors: q = tid&7 -> plane (q<4 hi, else lo) + 16B slice qq=q&3
    const int q = tid & 7, qq = q & 3, r0 = tid >> 3;
    const bool hiP = (q < 4);
    const __half* srcA[8]; int szA[8];
    uint32_t dA[8], dB[8];
    const __half* xPlane = hiP ? g_xh : g_xl;
    const __half* wPlane = (hiP ? g_w1h : g_w1l) + (size_t)e * DFF * DMODEL + (size_t)n0 * DMODEL;
    const __half* srcB[8];
    #pragma unroll
    for (int it = 0; it < 8; it++) {
        int r = r0 + 16 * it;
        int t = sTok[r];
        srcA[it] = xPlane + (size_t)(t < 0 ? 0 : t) * DMODEL + qq * 8;
        szA[it]  = (t >= 0) ? 16 : 0;
        srcB[it] = wPlane + (size_t)r * DMODEL + qq * 8;
        dA[it] = smem_u32 + ((hiP ? AH_OFF : AL_OFF) + r * SW + qq * 4) * 4;
        dB[it] = smem_u32 + ((hiP ? BH_OFF : BL_OFF) + r * SW + qq * 4) * 4;
    }

    const int NCHUNK = DMODEL / KC;   // 32
    const int wid = tid >> 5, lane = tid & 31;
    const int wm = wid >> 1, wn = wid & 1;
    const int g = lane >> 2, tg = lane & 3;

    float acc[4][8][4];
    #pragma unroll
    for (int i = 0; i < 4; i++)
        #pragma unroll
        for (int j = 0; j < 8; j++)
            #pragma unroll
            for (int k = 0; k < 4; k++) acc[i][j][k] = 0.f;

    // prologue: chunk 0 into stage 0
    #pragma unroll
    for (int it = 0; it < 8; it++) cp16(dA[it], srcA[it], szA[it]);
    #pragma unroll
    for (int it = 0; it < 8; it++) cp16(dB[it], srcB[it], 16);
    cp_commit();

    for (int i = 0; i < NCHUNK; i++) {
        int pc = i + 1;
        if (pc < NCHUNK) {
            uint32_t sb = (pc & 1) * (STAGE_W * 4);
            int k0 = pc * KC;
            #pragma unroll
            for (int it = 0; it < 8; it++) cp16(dA[it] + sb, srcA[it] + k0, szA[it]);
            #pragma unroll
            for (int it = 0; it < 8; it++) cp16(dB[it] + sb, srcB[it] + k0, 16);
        }
        cp_commit();
        cp_wait1();
        __syncthreads();

        compute_chunk(smem + (i & 1) * STAGE_W, wm, wn, g, tg, acc);
        __syncthreads();
    }

    const float* b1e = b1 + (size_t)e * DFF + n0;
    #pragma unroll
    for (int mt = 0; mt < 4; mt++) {
        int row = wm * 64 + mt * 16 + g;
        #pragma unroll
        for (int nt = 0; nt < 8; nt++) {
            int col = wn * 64 + nt * 8 + tg * 2;
            float bb0 = b1e[col], bb1 = b1e[col + 1];
            float y00 = fmaxf(acc[mt][nt][0] + bb0, 0.f);
            float y01 = fmaxf(acc[mt][nt][1] + bb1, 0.f);
            float y10 = fmaxf(acc[mt][nt][2] + bb0, 0.f);
            float y11 = fmaxf(acc[mt][nt][3] + bb1, 0.f);
            __half h00 = __float2half_rn(y00), h01 = __float2half_rn(y01);
            __half h10 = __float2half_rn(y10), h11 = __float2half_rn(y11);
            __half l00 = __float2half_rn(y00 - __half2float(h00));
            __half l01 = __float2half_rn(y01 - __half2float(h01));
            __half l10 = __float2half_rn(y10 - __half2float(h10));
            __half l11 = __float2half_rn(y11 - __half2float(h11));
            size_t o0 = (size_t)(base + row) * DFF + n0 + col;
            size_t o1 = (size_t)(base + row + 8) * DFF + n0 + col;
            *(__half2*)(g_hh + o0) = __halves2half2(h00, h01);
            *(__half2*)(g_hl + o0) = __halves2half2(l00, l01);
            *(__half2*)(g_hh + o1) = __halves2half2(h10, h11);
            *(__half2*)(g_hl + o1) = __halves2half2(l10, l11);
        }
    }
}

// ---------------- 6: gemm2  out[token] += gate * (h @ w2[e] + b2) ----------------
__global__ __launch_bounds__(NTHR, 2) void gemm2_kernel(
    const float* __restrict__ b2, float* __restrict__ out)
{
    const int tile = blockIdx.y;
    const int e = g_tile_expert[tile];
    if (e < 0) return;
    const int n0 = blockIdx.x * 128;
    const int base = tile * 128;

    extern __shared__ uint32_t smem[];
    __shared__ int   sTok[128];
    __shared__ float sGate[128];

    const int tid = threadIdx.x;
    sTok[tid]  = g_slot_token[base + tid];
    sGate[tid] = g_slot_gate[base + tid];
    __syncthreads();

    const uint32_t smem_u32 = (uint32_t)__cvta_generic_to_shared(smem);

    const int q = tid & 7, qq = q & 3, r0 = tid >> 3;
    const bool hiP = (q < 4);
    const __half* aPlane = (hiP ? g_hh : g_hl) + (size_t)base * DFF + qq * 8;
    const __half* wPlane = (hiP ? g_w2h : g_w2l) + (size_t)e * DMODEL * DFF + (size_t)n0 * DFF + qq * 8;
    const __half* srcA[8];
    const __half* srcB[8];
    uint32_t dA[8], dB[8];
    #pragma unroll
    for (int it = 0; it < 8; it++) {
        int r = r0 + 16 * it;
        srcA[it] = aPlane + (size_t)r * DFF;
        srcB[it] = wPlane + (size_t)r * DFF;
        dA[it] = smem_u32 + ((hiP ? AH_OFF : AL_OFF) + r * SW + qq * 4) * 4;
        dB[it] = smem_u32 + ((hiP ? BH_OFF : BL_OFF) + r * SW + qq * 4) * 4;
    }

    const int NCHUNK = DFF / KC;   // 128
    const int wid = tid >> 5, lane = tid & 31;
    const int wm = wid >> 1, wn = wid & 1;
    const int g = lane >> 2, tg = lane & 3;

    float acc[4][8][4];
    #pragma unroll
    for (int i = 0; i < 4; i++)
        #pragma unroll
        for (int j = 0; j < 8; j++)
            #pragma unroll
            for (int k = 0; k < 4; k++) acc[i][j][k] = 0.f;

    #pragma unroll
    for (int it = 0; it < 8; it++) cp16(dA[it], srcA[it], 16);
    #pragma unroll
    for (int it = 0; it < 8; it++) cp16(dB[it], srcB[it], 16);
    cp_commit();

    for (int i = 0; i < NCHUNK; i++) {
        int pc = i + 1;
        if (pc < NCHUNK) {
            uint32_t sb = (pc & 1) * (STAGE_W * 4);
            int k0 = pc * KC;
            #pragma unroll
            for (int it = 0; it < 8; it++) cp16(dA[it] + sb, srcA[it] + k0, 16);
            #pragma unroll
            for (int it = 0; it < 8; it++) cp16(dB[it] + sb, srcB[it] + k0, 16);
        }
        cp_commit();
        cp_wait1();
        __syncthreads();

        compute_chunk(smem + (i & 1) * STAGE_W, wm, wn, g, tg, acc);
        __syncthreads();
    }

    const float* b2e = b2 + (size_t)e * DMODEL + n0;
    #pragma unroll
    for (int mt = 0; mt < 4; mt++) {
        int row = wm * 64 + mt * 16 + g;
        int tk0 = sTok[row], tk1 = sTok[row + 8];
        float gt0 = sGate[row], gt1 = sGate[row + 8];
        #pragma unroll
        for (int nt = 0; nt < 8; nt++) {
            int col = wn * 64 + nt * 8 + tg * 2;
            float bb0 = b2e[col], bb1 = b2e[col + 1];
            if (tk0 >= 0) {
                atomicAdd(out + (size_t)tk0 * DMODEL + n0 + col,     gt0 * (acc[mt][nt][0] + bb0));
                atomicAdd(out + (size_t)tk0 * DMODEL + n0 + col + 1, gt0 * (acc[mt][nt][1] + bb1));
            }
            if (tk1 >= 0) {
                atomicAdd(out + (size_t)tk1 * DMODEL + n0 + col,     gt1 * (acc[mt][nt][2] + bb0));
                atomicAdd(out + (size_t)tk1 * DMODEL + n0 + col + 1, gt1 * (acc[mt][nt][3] + bb1));
            }
        }
    }
}

// ---------------- launch ----------------
extern "C" void kernel_launch(void* const* d_in, const int* in_sizes, int n_in,
                              void* d_out, int out_size)
{
    (void)in_sizes; (void)n_in; (void)out_size;
    const float* x       = (const float*)d_in[0];
    const float* noise_u = (const float*)d_in[1];
    const float* wg      = (const float*)d_in[2];
    const float* bg      = (const float*)d_in[3];
    const float* wn      = (const float*)d_in[4];
    const float* bn      = (const float*)d_in[5];
    const float* w1      = (const float*)d_in[6];
    const float* b1      = (const float*)d_in[7];
    const float* w2      = (const float*)d_in[8];
    const float* b2      = (const float*)d_in[9];
    float* out = (float*)d_out;

    __half *w1h, *w1l, *w2h, *w2l;
    cudaGetSymbolAddress((void**)&w1h, g_w1h);
    cudaGetSymbolAddress((void**)&w1l, g_w1l);
    cudaGetSymbolAddress((void**)&w2h, g_w2h);
    cudaGetSymbolAddress((void**)&w2l, g_w2l);

    cudaFuncSetAttribute(gemm1_kernel, cudaFuncAttributeMaxDynamicSharedMemorySize, SMEM_BYTES);
    cudaFuncSetAttribute(gemm2_kernel, cudaFuncAttributeMaxDynamicSharedMemorySize, SMEM_BYTES);

    reset_kernel<<<(MAX_SLOTS + 255) / 256, 256>>>();
    router_kernel<<<T_TOK / 8, 256>>>(x, noise_u, wg, bg, wn, bn);
    offsets_kernel<<<1, 32>>>();
    scatter_kernel<<<(T_TOK * 2) / 256, 256>>>();
    zero_out_kernel<<<(T_TOK * DMODEL) / (4 * 256), 256>>>((float4*)out);

    // fp16 hi/lo split pre-passes
    split_x_kernel<<<(int)(((size_t)T_TOK * DMODEL / 4) / 256), 256>>>((const float4*)x);
    {   // w1: [e][K=DMODEL][N=DFF] -> [e][N][K]
        dim3 gdim(DFF / 32, DMODEL / 32, NEXP), bdim(32, 8);
        split_w_kernel<<<gdim, bdim>>>(w1, w1h, w1l, DMODEL, DFF);
    }
    {   // w2: [e][K=DFF][N=DMODEL] -> [e][N][K]
        dim3 gdim(DMODEL / 32, DFF / 32, NEXP), bdim(32, 8);
        split_w_kernel<<<gdim, bdim>>>(w2, w2h, w2l, DFF, DMODEL);
    }

    gemm1_kernel<<<dim3(DFF / 128, MAX_TILES), NTHR, SMEM_BYTES>>>(b1);
    gemm2_kernel<<<dim3(DMODEL / 128, MAX_TILES), NTHR, SMEM_BYTES>>>(b2, out);
}

// round 12
// speedup vs baseline: 2.2241x; 2.2241x over previous
#include <cuda_runtime.h>
#include <cuda_fp16.h>
#include <cstdint>

#define T_TOK   8192
#define DMODEL  1024
#define DFF     4096
#define NEXP    8
#define MAX_SLOTS 17408          // 16384 assignments + per-expert pad to 128
#define MAX_TILES 136            // MAX_SLOTS / 128
#define KC 32                    // k halves per chunk (64 B per row)
#define SW 20                    // uint32 words per row (16 used + 4 pad)
#define PLANE_W (128 * SW)       // 2560 words per plane
#define A_OFF 0
#define B_OFF PLANE_W
#define STAGE_W (2 * PLANE_W)    // 5120 words = 20480 B
#define NSTAGE 3
#define NTHR 128                 // 4 warps per CTA, 2 CTAs/SM
#define SMEM_BYTES (NSTAGE * STAGE_W * 4)   // 61440 B

// ---------------- device scratch (no allocation allowed) ----------------
__device__ __half g_xh [(size_t)T_TOK * DMODEL];        // fp16 x (16 MB)
__device__ __half g_w1h[(size_t)NEXP * DFF * DMODEL];   // fp16 w1^T [e][n][k] (64 MB)
__device__ __half g_w2h[(size_t)NEXP * DMODEL * DFF];   // fp16 w2^T [e][n][k] (64 MB)
__device__ __half g_hh [(size_t)MAX_SLOTS * DFF];       // fp16 hidden acts (143 MB)
__device__ int   g_slot_token[MAX_SLOTS];
__device__ float g_slot_gate[MAX_SLOTS];
__device__ int   g_counts[NEXP];
__device__ int   g_fill[NEXP];
__device__ int   g_offsets[NEXP];
__device__ int   g_tile_expert[MAX_TILES];
__device__ int   g_tok_expert[T_TOK * 2];
__device__ float g_tok_gate[T_TOK * 2];

// ---------------- helpers ----------------
__device__ __forceinline__ void mma_f16(float c[4], const uint32_t a[4], const uint32_t b[2]) {
    asm volatile(
        "mma.sync.aligned.m16n8k16.row.col.f32.f16.f16.f32 "
        "{%0,%1,%2,%3}, {%4,%5,%6,%7}, {%8,%9}, {%0,%1,%2,%3};\n"
        : "+f"(c[0]), "+f"(c[1]), "+f"(c[2]), "+f"(c[3])
        : "r"(a[0]), "r"(a[1]), "r"(a[2]), "r"(a[3]), "r"(b[0]), "r"(b[1]));
}
__device__ __forceinline__ void cp16(uint32_t smem_addr, const void* gmem, int src_bytes) {
    asm volatile("cp.async.cg.shared.global [%0], [%1], 16, %2;\n"
                 :: "r"(smem_addr), "l"(gmem), "r"(src_bytes));
}
__device__ __forceinline__ void cp_commit() {
    asm volatile("cp.async.commit_group;\n" ::: "memory");
}
__device__ __forceinline__ void cp_wait1() {
    asm volatile("cp.async.wait_group 1;\n" ::: "memory");
}

// ---------------- 0: reset ----------------
__global__ void reset_kernel() {
    int i = blockIdx.x * 256 + threadIdx.x;
    if (i < MAX_SLOTS) g_slot_token[i] = -1;
    if (i < NEXP) { g_counts[i] = 0; g_fill[i] = 0; }
}

// ---------------- 0b: x -> fp16 ----------------
__global__ __launch_bounds__(256) void cvt_x_kernel(const float4* __restrict__ x) {
    size_t i = (size_t)blockIdx.x * 256 + threadIdx.x;
    float4 v = x[i];
    __half2* oh = (__half2*)(g_xh + 4 * i);
    oh[0] = __halves2half2(__float2half_rn(v.x), __float2half_rn(v.y));
    oh[1] = __halves2half2(__float2half_rn(v.z), __float2half_rn(v.w));
}

// ---------------- 0c: transpose + cvt weights: [e][K][N] f32 -> [e][N][K] fp16 ----------------
__global__ __launch_bounds__(256) void cvt_w_kernel(
    const float* __restrict__ src, __half* __restrict__ dh, int K, int N)
{
    __shared__ float tile[32][33];
    int e = blockIdx.z;
    const float* s = src + (size_t)e * K * N;
    __half* oh = dh + (size_t)e * K * N;
    int n0 = blockIdx.x * 32, k0 = blockIdx.y * 32;
    int tx = threadIdx.x, ty = threadIdx.y;   // 32 x 8
    #pragma unroll
    for (int j = 0; j < 32; j += 8)
        tile[ty + j][tx] = s[(size_t)(k0 + ty + j) * N + n0 + tx];
    __syncthreads();
    #pragma unroll
    for (int j = 0; j < 32; j += 8) {
        int n = n0 + ty + j;
        oh[(size_t)n * K + k0 + tx] = __float2half_rn(tile[tx][ty + j]);
    }
}

// ---------------- 1: router (one warp per token) ----------------
__global__ __launch_bounds__(256) void router_kernel(
    const float* __restrict__ x, const float* __restrict__ noise_u,
    const float* __restrict__ wg, const float* __restrict__ bg,
    const float* __restrict__ wn, const float* __restrict__ bn)
{
    __shared__ float sW[512][20];
    const int tid = threadIdx.x;
    const int wid = tid >> 5, lane = tid & 31;
    const int t = blockIdx.x * 8 + wid;

    float acc[16];
    #pragma unroll
    for (int j = 0; j < 16; j++) acc[j] = 0.f;

    for (int c = 0; c < 2; c++) {
        #pragma unroll
        for (int it = 0; it < 8; it++) {
            int idx = it * 256 + tid;
            int row = idx >> 2, qq = idx & 3;
            int grow = c * 512 + row;
            float4 v;
            if (qq < 2) v = *(const float4*)(wg + (size_t)grow * NEXP + qq * 4);
            else        v = *(const float4*)(wn + (size_t)grow * NEXP + (qq - 2) * 4);
            *(float4*)&sW[row][qq * 4] = v;
        }
        __syncthreads();

        const float* xr = x + (size_t)t * DMODEL + c * 512;
        for (int kk = lane; kk < 512; kk += 32) {
            float xv = xr[kk];
            float4 a0 = *(const float4*)&sW[kk][0];
            float4 a1 = *(const float4*)&sW[kk][4];
            float4 b0 = *(const float4*)&sW[kk][8];
            float4 b1 = *(const float4*)&sW[kk][12];
            acc[0]  += xv * a0.x; acc[1]  += xv * a0.y; acc[2]  += xv * a0.z; acc[3]  += xv * a0.w;
            acc[4]  += xv * a1.x; acc[5]  += xv * a1.y; acc[6]  += xv * a1.z; acc[7]  += xv * a1.w;
            acc[8]  += xv * b0.x; acc[9]  += xv * b0.y; acc[10] += xv * b0.z; acc[11] += xv * b0.w;
            acc[12] += xv * b1.x; acc[13] += xv * b1.y; acc[14] += xv * b1.z; acc[15] += xv * b1.w;
        }
        __syncthreads();
    }

    #pragma unroll
    for (int j = 0; j < 16; j++) {
        float v = acc[j];
        #pragma unroll
        for (int o = 16; o > 0; o >>= 1) v += __shfl_xor_sync(0xffffffffu, v, o);
        acc[j] = v;
    }

    if (lane == 0) {
        float v0 = -1e30f, v1 = -1e30f;
        int i0 = 0, i1 = 0;
        #pragma unroll
        for (int e = 0; e < NEXP; e++) {
            float lg = acc[e] + bg[e];
            float nl = acc[8 + e] + bn[e];
            float sp = fmaxf(nl, 0.f) + log1pf(expf(-fabsf(nl)));
            float nz = lg + noise_u[(size_t)t * NEXP + e] * sp;
            if (nz > v0)      { v1 = v0; i1 = i0; v0 = nz; i0 = e; }
            else if (nz > v1) { v1 = nz; i1 = e; }
        }
        float e1 = expf(v1 - v0);
        float s  = 1.f + e1;
        int o = t * 2;
        g_tok_expert[o]     = i0; g_tok_gate[o]     = 1.f / s;
        g_tok_expert[o + 1] = i1; g_tok_gate[o + 1] = e1 / s;
        atomicAdd(&g_counts[i0], 1);
        atomicAdd(&g_counts[i1], 1);
    }
}

// ---------------- 2: offsets ----------------
__global__ void offsets_kernel() {
    if (threadIdx.x == 0 && blockIdx.x == 0) {
        int off = 0;
        for (int e = 0; e < NEXP; e++) {
            g_offsets[e] = off;
            int tiles = (g_counts[e] + 127) >> 7;
            for (int i = 0; i < tiles; i++) g_tile_expert[(off >> 7) + i] = e;
            off += tiles << 7;
        }
        for (int i = off >> 7; i < MAX_TILES; i++) g_tile_expert[i] = -1;
    }
}

// ---------------- 3: scatter ----------------
__global__ void scatter_kernel() {
    int i = blockIdx.x * 256 + threadIdx.x;
    if (i >= T_TOK * 2) return;
    int e = g_tok_expert[i];
    float gt = g_tok_gate[i];
    int pos = atomicAdd(&g_fill[e], 1);
    int slot = g_offsets[e] + pos;
    g_slot_token[slot] = i >> 1;
    g_slot_gate[slot]  = gt;
}

// ---------------- 4: zero output ----------------
__global__ void zero_out_kernel(float4* __restrict__ out) {
    out[(size_t)blockIdx.x * 256 + threadIdx.x] = make_float4(0.f, 0.f, 0.f, 0.f);
}

// ================= plain-fp16 GEMM core: 4 warps (2m x 2n), 64x64 warp tiles =================
// Stage (uint32 words): A[128][SW], B[128][SW]. Rows k-contiguous (A rows = m, B rows = n).
// Per chunk: 2 k16-steps, 32 MMAs each -> 64 MMAs/warp (half of tf32's 128).
__device__ __forceinline__ void compute_chunk(
    const uint32_t* __restrict__ S, int wm, int wn, int g, int tg, float acc[4][8][4])
{
    #pragma unroll
    for (int step = 0; step < 2; step++) {
        const int kw = step * 8 + tg;
        uint32_t a[4][4], b[8][2];
        #pragma unroll
        for (int mt = 0; mt < 4; mt++) {
            int base = (wm * 64 + mt * 16 + g) * SW + kw;
            a[mt][0] = S[A_OFF + base];
            a[mt][1] = S[A_OFF + base + 8 * SW];
            a[mt][2] = S[A_OFF + base + 4];
            a[mt][3] = S[A_OFF + base + 8 * SW + 4];
        }
        #pragma unroll
        for (int nt = 0; nt < 8; nt++) {
            int base = (wn * 64 + nt * 8 + g) * SW + kw;
            b[nt][0] = S[B_OFF + base];
            b[nt][1] = S[B_OFF + base + 4];
        }
        #pragma unroll
        for (int mt = 0; mt < 4; mt++)
            #pragma unroll
            for (int nt = 0; nt < 8; nt++)
                mma_f16(acc[mt][nt], a[mt], b[nt]);
    }
}

// ---------------- 5: gemm1  h = fp16(relu(gather(X) @ w1[e] + b1)) ----------------
__global__ __launch_bounds__(NTHR, 2) void gemm1_kernel(const float* __restrict__ b1)
{
    const int tile = blockIdx.y;
    const int e = g_tile_expert[tile];
    if (e < 0) return;
    const int n0 = blockIdx.x * 128;
    const int base = tile * 128;

    extern __shared__ uint32_t smem[];
    __shared__ int sTok[128];

    const int tid = threadIdx.x;
    sTok[tid] = g_slot_token[base + tid];
    __syncthreads();

    const uint32_t smem_u32 = (uint32_t)__cvta_generic_to_shared(smem);

    // fetch: qq = tid&3 (16B slice of 64B row), r0 = tid>>2 (32 rows), 4 its -> 128 rows
    const int qq = tid & 3, r0 = tid >> 2;
    const __half* srcA[4]; int szA[4];
    const __half* srcB[4];
    uint32_t dA[4], dB[4];
    const __half* wPlane = g_w1h + (size_t)e * DFF * DMODEL + (size_t)n0 * DMODEL;
    #pragma unroll
    for (int it = 0; it < 4; it++) {
        int r = r0 + 32 * it;
        int t = sTok[r];
        srcA[it] = g_xh + (size_t)(t < 0 ? 0 : t) * DMODEL + qq * 8;
        szA[it]  = (t >= 0) ? 16 : 0;
        srcB[it] = wPlane + (size_t)r * DMODEL + qq * 8;
        dA[it] = smem_u32 + ((A_OFF + r * SW + qq * 4) << 2);
        dB[it] = smem_u32 + ((B_OFF + r * SW + qq * 4) << 2);
    }

    const int NCHUNK = DMODEL / KC;   // 32
    const int wid = tid >> 5, lane = tid & 31;
    const int wm = wid >> 1, wn = wid & 1;
    const int g = lane >> 2, tg = lane & 3;

    float acc[4][8][4];
    #pragma unroll
    for (int i = 0; i < 4; i++)
        #pragma unroll
        for (int j = 0; j < 8; j++)
            #pragma unroll
            for (int k = 0; k < 4; k++) acc[i][j][k] = 0.f;

    // prologue: chunks 0 and 1 into stages 0, 1
    #pragma unroll
    for (int p = 0; p < 2; p++) {
        uint32_t sb = p * (STAGE_W * 4);
        int k0 = p * KC;
        #pragma unroll
        for (int it = 0; it < 4; it++) cp16(dA[it] + sb, srcA[it] + k0, szA[it]);
        #pragma unroll
        for (int it = 0; it < 4; it++) cp16(dB[it] + sb, srcB[it] + k0, 16);
        cp_commit();
    }

    for (int i = 0; i < NCHUNK; i++) {
        cp_wait1();            // chunk i complete (chunk i+1 may be in flight)
        __syncthreads();       // data visible; stage (i+2)%3 no longer being read
        int pc = i + 2;
        if (pc < NCHUNK) {
            uint32_t sb = (pc % NSTAGE) * (STAGE_W * 4);
            int k0 = pc * KC;
            #pragma unroll
            for (int it = 0; it < 4; it++) cp16(dA[it] + sb, srcA[it] + k0, szA[it]);
            #pragma unroll
            for (int it = 0; it < 4; it++) cp16(dB[it] + sb, srcB[it] + k0, 16);
        }
        cp_commit();
        compute_chunk(smem + (i % NSTAGE) * STAGE_W, wm, wn, g, tg, acc);
    }

    const float* b1e = b1 + (size_t)e * DFF + n0;
    #pragma unroll
    for (int mt = 0; mt < 4; mt++) {
        int row = wm * 64 + mt * 16 + g;
        #pragma unroll
        for (int nt = 0; nt < 8; nt++) {
            int col = wn * 64 + nt * 8 + tg * 2;
            float bb0 = b1e[col], bb1 = b1e[col + 1];
            float y00 = fmaxf(acc[mt][nt][0] + bb0, 0.f);
            float y01 = fmaxf(acc[mt][nt][1] + bb1, 0.f);
            float y10 = fmaxf(acc[mt][nt][2] + bb0, 0.f);
            float y11 = fmaxf(acc[mt][nt][3] + bb1, 0.f);
            size_t o0 = (size_t)(base + row) * DFF + n0 + col;
            size_t o1 = (size_t)(base + row + 8) * DFF + n0 + col;
            *(__half2*)(g_hh + o0) = __halves2half2(__float2half_rn(y00), __float2half_rn(y01));
            *(__half2*)(g_hh + o1) = __halves2half2(__float2half_rn(y10), __float2half_rn(y11));
        }
    }
}

// ---------------- 6: gemm2  out[token] += gate * (h @ w2[e] + b2) ----------------
__global__ __launch_bounds__(NTHR, 2) void gemm2_kernel(
    const float* __restrict__ b2, float* __restrict__ out)
{
    const int tile = blockIdx.y;
    const int e = g_tile_expert[tile];
    if (e < 0) return;
    const int n0 = blockIdx.x * 128;
    const int base = tile * 128;

    extern __shared__ uint32_t smem[];
    __shared__ int   sTok[128];
    __shared__ float sGate[128];

    const int tid = threadIdx.x;
    sTok[tid]  = g_slot_token[base + tid];
    sGate[tid] = g_slot_gate[base + tid];
    __syncthreads();

    const uint32_t smem_u32 = (uint32_t)__cvta_generic_to_shared(smem);

    const int qq = tid & 3, r0 = tid >> 2;
    const __half* srcA[4];
    const __half* srcB[4];
    uint32_t dA[4], dB[4];
    const __half* aPlane = g_hh + (size_t)base * DFF + qq * 8;
    const __half* wPlane = g_w2h + (size_t)e * DMODEL * DFF + (size_t)n0 * DFF + qq * 8;
    #pragma unroll
    for (int it = 0; it < 4; it++) {
        int r = r0 + 32 * it;
        srcA[it] = aPlane + (size_t)r * DFF;
        srcB[it] = wPlane + (size_t)r * DFF;
        dA[it] = smem_u32 + ((A_OFF + r * SW + qq * 4) << 2);
        dB[it] = smem_u32 + ((B_OFF + r * SW + qq * 4) << 2);
    }

    const int NCHUNK = DFF / KC;   // 128
    const int wid = tid >> 5, lane = tid & 31;
    const int wm = wid >> 1, wn = wid & 1;
    const int g = lane >> 2, tg = lane & 3;

    float acc[4][8][4];
    #pragma unroll
    for (int i = 0; i < 4; i++)
        #pragma unroll
        for (int j = 0; j < 8; j++)
            #pragma unroll
            for (int k = 0; k < 4; k++) acc[i][j][k] = 0.f;

    #pragma unroll
    for (int p = 0; p < 2; p++) {
        uint32_t sb = p * (STAGE_W * 4);
        int k0 = p * KC;
        #pragma unroll
        for (int it = 0; it < 4; it++) cp16(dA[it] + sb, srcA[it] + k0, 16);
        #pragma unroll
        for (int it = 0; it < 4; it++) cp16(dB[it] + sb, srcB[it] + k0, 16);
        cp_commit();
    }

    for (int i = 0; i < NCHUNK; i++) {
        cp_wait1();
        __syncthreads();
        int pc = i + 2;
        if (pc < NCHUNK) {
            uint32_t sb = (pc % NSTAGE) * (STAGE_W * 4);
            int k0 = pc * KC;
            #pragma unroll
            for (int it = 0; it < 4; it++) cp16(dA[it] + sb, srcA[it] + k0, 16);
            #pragma unroll
            for (int it = 0; it < 4; it++) cp16(dB[it] + sb, srcB[it] + k0, 16);
        }
        cp_commit();
        compute_chunk(smem + (i % NSTAGE) * STAGE_W, wm, wn, g, tg, acc);
    }

    const float* b2e = b2 + (size_t)e * DMODEL + n0;
    #pragma unroll
    for (int mt = 0; mt < 4; mt++) {
        int row = wm * 64 + mt * 16 + g;
        int tk0 = sTok[row], tk1 = sTok[row + 8];
        float gt0 = sGate[row], gt1 = sGate[row + 8];
        #pragma unroll
        for (int nt = 0; nt < 8; nt++) {
            int col = wn * 64 + nt * 8 + tg * 2;
            float bb0 = b2e[col], bb1 = b2e[col + 1];
            if (tk0 >= 0) {
                atomicAdd(out + (size_t)tk0 * DMODEL + n0 + col,     gt0 * (acc[mt][nt][0] + bb0));
                atomicAdd(out + (size_t)tk0 * DMODEL + n0 + col + 1, gt0 * (acc[mt][nt][1] + bb1));
            }
            if (tk1 >= 0) {
                atomicAdd(out + (size_t)tk1 * DMODEL + n0 + col,     gt1 * (acc[mt][nt][2] + bb0));
                atomicAdd(out + (size_t)tk1 * DMODEL + n0 + col + 1, gt1 * (acc[mt][nt][3] + bb1));
            }
        }
    }
}

// ---------------- launch ----------------
extern "C" void kernel_launch(void* const* d_in, const int* in_sizes, int n_in,
                              void* d_out, int out_size)
{
    (void)in_sizes; (void)n_in; (void)out_size;
    const float* x       = (const float*)d_in[0];
    const float* noise_u = (const float*)d_in[1];
    const float* wg      = (const float*)d_in[2];
    const float* bg      = (const float*)d_in[3];
    const float* wn      = (const float*)d_in[4];
    const float* bn      = (const float*)d_in[5];
    const float* w1      = (const float*)d_in[6];
    const float* b1      = (const float*)d_in[7];
    const float* w2      = (const float*)d_in[8];
    const float* b2      = (const float*)d_in[9];
    float* out = (float*)d_out;

    __half *w1h, *w2h;
    cudaGetSymbolAddress((void**)&w1h, g_w1h);
    cudaGetSymbolAddress((void**)&w2h, g_w2h);

    cudaFuncSetAttribute(gemm1_kernel, cudaFuncAttributeMaxDynamicSharedMemorySize, SMEM_BYTES);
    cudaFuncSetAttribute(gemm2_kernel, cudaFuncAttributeMaxDynamicSharedMemorySize, SMEM_BYTES);

    reset_kernel<<<(MAX_SLOTS + 255) / 256, 256>>>();
    router_kernel<<<T_TOK / 8, 256>>>(x, noise_u, wg, bg, wn, bn);
    offsets_kernel<<<1, 32>>>();
    scatter_kernel<<<(T_TOK * 2) / 256, 256>>>();
    zero_out_kernel<<<(T_TOK * DMODEL) / (4 * 256), 256>>>((float4*)out);

    // fp16 conversion pre-passes
    cvt_x_kernel<<<(int)(((size_t)T_TOK * DMODEL / 4) / 256), 256>>>((const float4*)x);
    {   // w1: [e][K=DMODEL][N=DFF] -> [e][N][K] fp16
        dim3 gdim(DFF / 32, DMODEL / 32, NEXP), bdim(32, 8);
        cvt_w_kernel<<<gdim, bdim>>>(w1, w1h, DMODEL, DFF);
    }
    {   // w2: [e][K=DFF][N=DMODEL] -> [e][N][K] fp16
        dim3 gdim(DMODEL / 32, DFF / 32, NEXP), bdim(32, 8);
        cvt_w_kernel<<<gdim, bdim>>>(w2, w2h, DFF, DMODEL);
    }

    gemm1_kernel<<<dim3(DFF / 128, MAX_TILES), NTHR, SMEM_BYTES>>>(b1);
    gemm2_kernel<<<dim3(DMODEL / 128, MAX_TILES), NTHR, SMEM_BYTES>>>(b2, out);
}

// round 13
// speedup vs baseline: 2.4949x; 1.1218x over previous
#include <cuda_runtime.h>
#include <cuda_fp16.h>
#include <cstdint>

#define T_TOK   8192
#define DMODEL  1024
#define DFF     4096
#define NEXP    8
#define MAX_SLOTS 17408          // 16384 assignments + per-expert pad to 128
#define MAX_TILES 136            // MAX_SLOTS / 128
#define KC 64                    // k halves per chunk (128 B per row)
#define SW 36                    // uint32 words per row (32 used + 4 pad); banks (4g+tg) distinct
#define PLANE_W (128 * SW)       // 4608 words per plane
#define A_OFF 0
#define B_OFF PLANE_W
#define STAGE_W (2 * PLANE_W)    // 9216 words = 36864 B
#define NSTAGE 2
#define NTHR 128                 // 4 warps per CTA, 2 CTAs/SM
#define SMEM_BYTES (NSTAGE * STAGE_W * 4)   // 73728 B

// ---------------- device scratch (no allocation allowed) ----------------
__device__ __half g_xh [(size_t)T_TOK * DMODEL];        // fp16 x (16 MB)
__device__ __half g_w1h[(size_t)NEXP * DFF * DMODEL];   // fp16 w1^T [e][n][k] (64 MB)
__device__ __half g_w2h[(size_t)NEXP * DMODEL * DFF];   // fp16 w2^T [e][n][k] (64 MB)
__device__ __half g_hh [(size_t)MAX_SLOTS * DFF];       // fp16 hidden acts (143 MB)
__device__ float  g_y  [(size_t)MAX_SLOTS * DMODEL];    // gated per-slot outputs (71 MB)
__device__ int   g_slot_token[MAX_SLOTS];
__device__ float g_slot_gate[MAX_SLOTS];
__device__ int   g_tok_slot[T_TOK * 2];                 // slot of each (token, k) assignment
__device__ int   g_counts[NEXP];
__device__ int   g_fill[NEXP];
__device__ int   g_offsets[NEXP];
__device__ int   g_tile_expert[MAX_TILES];
__device__ int   g_tok_expert[T_TOK * 2];
__device__ float g_tok_gate[T_TOK * 2];

// ---------------- helpers ----------------
__device__ __forceinline__ void mma_f16(float c[4], const uint32_t a[4], const uint32_t b[2]) {
    asm volatile(
        "mma.sync.aligned.m16n8k16.row.col.f32.f16.f16.f32 "
        "{%0,%1,%2,%3}, {%4,%5,%6,%7}, {%8,%9}, {%0,%1,%2,%3};\n"
        : "+f"(c[0]), "+f"(c[1]), "+f"(c[2]), "+f"(c[3])
        : "r"(a[0]), "r"(a[1]), "r"(a[2]), "r"(a[3]), "r"(b[0]), "r"(b[1]));
}
__device__ __forceinline__ void cp16(uint32_t smem_addr, const void* gmem, int src_bytes) {
    asm volatile("cp.async.cg.shared.global [%0], [%1], 16, %2;\n"
                 :: "r"(smem_addr), "l"(gmem), "r"(src_bytes));
}
__device__ __forceinline__ void cp_commit() {
    asm volatile("cp.async.commit_group;\n" ::: "memory");
}
__device__ __forceinline__ void cp_wait0() {
    asm volatile("cp.async.wait_group 0;\n" ::: "memory");
}

// ---------------- 0: reset ----------------
__global__ void reset_kernel() {
    int i = blockIdx.x * 256 + threadIdx.x;
    if (i < MAX_SLOTS) g_slot_token[i] = -1;
    if (i < NEXP) { g_counts[i] = 0; g_fill[i] = 0; }
}

// ---------------- 0b: x -> fp16 ----------------
__global__ __launch_bounds__(256) void cvt_x_kernel(const float4* __restrict__ x) {
    size_t i = (size_t)blockIdx.x * 256 + threadIdx.x;
    float4 v = x[i];
    __half2* oh = (__half2*)(g_xh + 4 * i);
    oh[0] = __halves2half2(__float2half_rn(v.x), __float2half_rn(v.y));
    oh[1] = __halves2half2(__float2half_rn(v.z), __float2half_rn(v.w));
}

// ---------------- 0c: transpose + cvt weights: [e][K][N] f32 -> [e][N][K] fp16 ----------------
__global__ __launch_bounds__(256) void cvt_w_kernel(
    const float* __restrict__ src, __half* __restrict__ dh, int K, int N)
{
    __shared__ float tile[32][33];
    int e = blockIdx.z;
    const float* s = src + (size_t)e * K * N;
    __half* oh = dh + (size_t)e * K * N;
    int n0 = blockIdx.x * 32, k0 = blockIdx.y * 32;
    int tx = threadIdx.x, ty = threadIdx.y;   // 32 x 8
    #pragma unroll
    for (int j = 0; j < 32; j += 8)
        tile[ty + j][tx] = s[(size_t)(k0 + ty + j) * N + n0 + tx];
    __syncthreads();
    #pragma unroll
    for (int j = 0; j < 32; j += 8) {
        int n = n0 + ty + j;
        oh[(size_t)n * K + k0 + tx] = __float2half_rn(tile[tx][ty + j]);
    }
}

// ---------------- 1: router (one warp per token) ----------------
__global__ __launch_bounds__(256) void router_kernel(
    const float* __restrict__ x, const float* __restrict__ noise_u,
    const float* __restrict__ wg, const float* __restrict__ bg,
    const float* __restrict__ wn, const float* __restrict__ bn)
{
    __shared__ float sW[512][20];
    const int tid = threadIdx.x;
    const int wid = tid >> 5, lane = tid & 31;
    const int t = blockIdx.x * 8 + wid;

    float acc[16];
    #pragma unroll
    for (int j = 0; j < 16; j++) acc[j] = 0.f;

    for (int c = 0; c < 2; c++) {
        #pragma unroll
        for (int it = 0; it < 8; it++) {
            int idx = it * 256 + tid;
            int row = idx >> 2, qq = idx & 3;
            int grow = c * 512 + row;
            float4 v;
            if (qq < 2) v = *(const float4*)(wg + (size_t)grow * NEXP + qq * 4);
            else        v = *(const float4*)(wn + (size_t)grow * NEXP + (qq - 2) * 4);
            *(float4*)&sW[row][qq * 4] = v;
        }
        __syncthreads();

        const float* xr = x + (size_t)t * DMODEL + c * 512;
        for (int kk = lane; kk < 512; kk += 32) {
            float xv = xr[kk];
            float4 a0 = *(const float4*)&sW[kk][0];
            float4 a1 = *(const float4*)&sW[kk][4];
            float4 b0 = *(const float4*)&sW[kk][8];
            float4 b1 = *(const float4*)&sW[kk][12];
            acc[0]  += xv * a0.x; acc[1]  += xv * a0.y; acc[2]  += xv * a0.z; acc[3]  += xv * a0.w;
            acc[4]  += xv * a1.x; acc[5]  += xv * a1.y; acc[6]  += xv * a1.z; acc[7]  += xv * a1.w;
            acc[8]  += xv * b0.x; acc[9]  += xv * b0.y; acc[10] += xv * b0.z; acc[11] += xv * b0.w;
            acc[12] += xv * b1.x; acc[13] += xv * b1.y; acc[14] += xv * b1.z; acc[15] += xv * b1.w;
        }
        __syncthreads();
    }

    #pragma unroll
    for (int j = 0; j < 16; j++) {
        float v = acc[j];
        #pragma unroll
        for (int o = 16; o > 0; o >>= 1) v += __shfl_xor_sync(0xffffffffu, v, o);
        acc[j] = v;
    }

    if (lane == 0) {
        float v0 = -1e30f, v1 = -1e30f;
        int i0 = 0, i1 = 0;
        #pragma unroll
        for (int e = 0; e < NEXP; e++) {
            float lg = acc[e] + bg[e];
            float nl = acc[8 + e] + bn[e];
            float sp = fmaxf(nl, 0.f) + log1pf(expf(-fabsf(nl)));
            float nz = lg + noise_u[(size_t)t * NEXP + e] * sp;
            if (nz > v0)      { v1 = v0; i1 = i0; v0 = nz; i0 = e; }
            else if (nz > v1) { v1 = nz; i1 = e; }
        }
        float e1 = expf(v1 - v0);
        float s  = 1.f + e1;
        int o = t * 2;
        g_tok_expert[o]     = i0; g_tok_gate[o]     = 1.f / s;
        g_tok_expert[o + 1] = i1; g_tok_gate[o + 1] = e1 / s;
        atomicAdd(&g_counts[i0], 1);
        atomicAdd(&g_counts[i1], 1);
    }
}

// ---------------- 2: offsets ----------------
__global__ void offsets_kernel() {
    if (threadIdx.x == 0 && blockIdx.x == 0) {
        int off = 0;
        for (int e = 0; e < NEXP; e++) {
            g_offsets[e] = off;
            int tiles = (g_counts[e] + 127) >> 7;
            for (int i = 0; i < tiles; i++) g_tile_expert[(off >> 7) + i] = e;
            off += tiles << 7;
        }
        for (int i = off >> 7; i < MAX_TILES; i++) g_tile_expert[i] = -1;
    }
}

// ---------------- 3: scatter ----------------
__global__ void scatter_kernel() {
    int i = blockIdx.x * 256 + threadIdx.x;
    if (i >= T_TOK * 2) return;
    int e = g_tok_expert[i];
    float gt = g_tok_gate[i];
    int pos = atomicAdd(&g_fill[e], 1);
    int slot = g_offsets[e] + pos;
    g_slot_token[slot] = i >> 1;
    g_slot_gate[slot]  = gt;
    g_tok_slot[i]      = slot;
}

// ================= plain-fp16 GEMM core: 4 warps (2m x 2n), 64x64 warp tiles =================
// Stage (uint32 words): A[128][SW], B[128][SW]. Rows k-contiguous (A rows = m, B rows = n).
// KC=64 -> 4 k16-steps, 32 MMAs each -> 128 MMAs/warp per chunk.
__device__ __forceinline__ void compute_chunk(
    const uint32_t* __restrict__ S, int wm, int wn, int g, int tg, float acc[4][8][4])
{
    #pragma unroll
    for (int step = 0; step < 4; step++) {
        const int kw = step * 8 + tg;
        uint32_t a[4][4], b[8][2];
        #pragma unroll
        for (int mt = 0; mt < 4; mt++) {
            int base = (wm * 64 + mt * 16 + g) * SW + kw;
            a[mt][0] = S[A_OFF + base];
            a[mt][1] = S[A_OFF + base + 8 * SW];
            a[mt][2] = S[A_OFF + base + 4];
            a[mt][3] = S[A_OFF + base + 8 * SW + 4];
        }
        #pragma unroll
        for (int nt = 0; nt < 8; nt++) {
            int base = (wn * 64 + nt * 8 + g) * SW + kw;
            b[nt][0] = S[B_OFF + base];
            b[nt][1] = S[B_OFF + base + 4];
        }
        #pragma unroll
        for (int mt = 0; mt < 4; mt++)
            #pragma unroll
            for (int nt = 0; nt < 8; nt++)
                mma_f16(acc[mt][nt], a[mt], b[nt]);
    }
}

// ---------------- 5: gemm1  h = fp16(relu(gather(X) @ w1[e] + b1)) ----------------
__global__ __launch_bounds__(NTHR, 2) void gemm1_kernel(const float* __restrict__ b1)
{
    const int tile = blockIdx.y;
    const int e = g_tile_expert[tile];
    if (e < 0) return;
    const int n0 = blockIdx.x * 128;
    const int base = tile * 128;

    extern __shared__ uint32_t smem[];
    __shared__ int sTok[128];

    const int tid = threadIdx.x;
    sTok[tid] = g_slot_token[base + tid];
    __syncthreads();

    const uint32_t smem_u32 = (uint32_t)__cvta_generic_to_shared(smem);

    // fetch: qq = tid&7 (16B slice of 128B row), r0 = tid>>3 (16 rows/it), 8 its -> 128 rows
    const int qq = tid & 7, r0 = tid >> 3;
    const __half* srcA[8]; int szA[8];
    #pragma unroll
    for (int it = 0; it < 8; it++) {
        int r = r0 + 16 * it;
        int t = sTok[r];
        srcA[it] = g_xh + (size_t)(t < 0 ? 0 : t) * DMODEL + qq * 8;
        szA[it]  = (t >= 0) ? 16 : 0;
    }
    const __half* srcB0 = g_w1h + (size_t)e * DFF * DMODEL + (size_t)(n0 + r0) * DMODEL + qq * 8;
    const uint32_t dA0 = smem_u32 + ((A_OFF + r0 * SW + qq * 4) << 2);
    const uint32_t dB0 = smem_u32 + ((B_OFF + r0 * SW + qq * 4) << 2);

    const int NCHUNK = DMODEL / KC;   // 16
    const int wid = tid >> 5, lane = tid & 31;
    const int wm = wid >> 1, wn = wid & 1;
    const int g = lane >> 2, tg = lane & 3;

    float acc[4][8][4];
    #pragma unroll
    for (int i = 0; i < 4; i++)
        #pragma unroll
        for (int j = 0; j < 8; j++)
            #pragma unroll
            for (int k = 0; k < 4; k++) acc[i][j][k] = 0.f;

    // prologue: chunk 0 into stage 0
    #pragma unroll
    for (int it = 0; it < 8; it++) cp16(dA0 + it * (16 * SW * 4), srcA[it], szA[it]);
    #pragma unroll
    for (int it = 0; it < 8; it++) cp16(dB0 + it * (16 * SW * 4), srcB0 + (size_t)it * 16 * DMODEL, 16);
    cp_commit();

    for (int i = 0; i < NCHUNK; i++) {
        cp_wait0();            // chunk i complete
        __syncthreads();       // visible to all; stage (i+1)&1 no longer being read
        int pc = i + 1;
        if (pc < NCHUNK) {
            uint32_t sb = (pc & 1) * (STAGE_W * 4);
            int k0 = pc * KC;
            #pragma unroll
            for (int it = 0; it < 8; it++)
                cp16(dA0 + sb + it * (16 * SW * 4), srcA[it] + k0, szA[it]);
            #pragma unroll
            for (int it = 0; it < 8; it++)
                cp16(dB0 + sb + it * (16 * SW * 4), srcB0 + (size_t)it * 16 * DMODEL + k0, 16);
        }
        cp_commit();
        compute_chunk(smem + (i & 1) * STAGE_W, wm, wn, g, tg, acc);
    }

    const float* b1e = b1 + (size_t)e * DFF + n0;
    #pragma unroll
    for (int mt = 0; mt < 4; mt++) {
        int row = wm * 64 + mt * 16 + g;
        #pragma unroll
        for (int nt = 0; nt < 8; nt++) {
            int col = wn * 64 + nt * 8 + tg * 2;
            float bb0 = b1e[col], bb1 = b1e[col + 1];
            float y00 = fmaxf(acc[mt][nt][0] + bb0, 0.f);
            float y01 = fmaxf(acc[mt][nt][1] + bb1, 0.f);
            float y10 = fmaxf(acc[mt][nt][2] + bb0, 0.f);
            float y11 = fmaxf(acc[mt][nt][3] + bb1, 0.f);
            size_t o0 = (size_t)(base + row) * DFF + n0 + col;
            size_t o1 = (size_t)(base + row + 8) * DFF + n0 + col;
            *(__half2*)(g_hh + o0) = __halves2half2(__float2half_rn(y00), __float2half_rn(y01));
            *(__half2*)(g_hh + o1) = __halves2half2(__float2half_rn(y10), __float2half_rn(y11));
        }
    }
}

// ---------------- 6: gemm2  y[slot] = gate * (h @ w2[e] + b2)  (no atomics) ----------------
__global__ __launch_bounds__(NTHR, 2) void gemm2_kernel(const float* __restrict__ b2)
{
    const int tile = blockIdx.y;
    const int e = g_tile_expert[tile];
    if (e < 0) return;
    const int n0 = blockIdx.x * 128;
    const int base = tile * 128;

    extern __shared__ uint32_t smem[];
    __shared__ float sGate[128];

    const int tid = threadIdx.x;
    sGate[tid] = g_slot_gate[base + tid];
    __syncthreads();

    const uint32_t smem_u32 = (uint32_t)__cvta_generic_to_shared(smem);

    const int qq = tid & 7, r0 = tid >> 3;
    const __half* srcA0 = g_hh + (size_t)(base + r0) * DFF + qq * 8;
    const __half* srcB0 = g_w2h + (size_t)e * DMODEL * DFF + (size_t)(n0 + r0) * DFF + qq * 8;
    const uint32_t dA0 = smem_u32 + ((A_OFF + r0 * SW + qq * 4) << 2);
    const uint32_t dB0 = smem_u32 + ((B_OFF + r0 * SW + qq * 4) << 2);

    const int NCHUNK = DFF / KC;   // 64
    const int wid = tid >> 5, lane = tid & 31;
    const int wm = wid >> 1, wn = wid & 1;
    const int g = lane >> 2, tg = lane & 3;

    float acc[4][8][4];
    #pragma unroll
    for (int i = 0; i < 4; i++)
        #pragma unroll
        for (int j = 0; j < 8; j++)
            #pragma unroll
            for (int k = 0; k < 4; k++) acc[i][j][k] = 0.f;

    #pragma unroll
    for (int it = 0; it < 8; it++) cp16(dA0 + it * (16 * SW * 4), srcA0 + (size_t)it * 16 * DFF, 16);
    #pragma unroll
    for (int it = 0; it < 8; it++) cp16(dB0 + it * (16 * SW * 4), srcB0 + (size_t)it * 16 * DFF, 16);
    cp_commit();

    for (int i = 0; i < NCHUNK; i++) {
        cp_wait0();
        __syncthreads();
        int pc = i + 1;
        if (pc < NCHUNK) {
            uint32_t sb = (pc & 1) * (STAGE_W * 4);
            int k0 = pc * KC;
            #pragma unroll
            for (int it = 0; it < 8; it++)
                cp16(dA0 + sb + it * (16 * SW * 4), srcA0 + (size_t)it * 16 * DFF + k0, 16);
            #pragma unroll
            for (int it = 0; it < 8; it++)
                cp16(dB0 + sb + it * (16 * SW * 4), srcB0 + (size_t)it * 16 * DFF + k0, 16);
        }
        cp_commit();
        compute_chunk(smem + (i & 1) * STAGE_W, wm, wn, g, tg, acc);
    }

    const float* b2e = b2 + (size_t)e * DMODEL + n0;
    #pragma unroll
    for (int mt = 0; mt < 4; mt++) {
        int row = wm * 64 + mt * 16 + g;
        float gt0 = sGate[row], gt1 = sGate[row + 8];
        float* y0 = g_y + (size_t)(base + row) * DMODEL + n0;
        float* y1 = g_y + (size_t)(base + row + 8) * DMODEL + n0;
        #pragma unroll
        for (int nt = 0; nt < 8; nt++) {
            int col = wn * 64 + nt * 8 + tg * 2;
            float bb0 = b2e[col], bb1 = b2e[col + 1];
            float2 v0, v1;
            v0.x = gt0 * (acc[mt][nt][0] + bb0);
            v0.y = gt0 * (acc[mt][nt][1] + bb1);
            v1.x = gt1 * (acc[mt][nt][2] + bb0);
            v1.y = gt1 * (acc[mt][nt][3] + bb1);
            *(float2*)(y0 + col) = v0;
            *(float2*)(y1 + col) = v1;
        }
    }
}

// ---------------- 7: combine  out[t] = y[slot0(t)] + y[slot1(t)] ----------------
__global__ __launch_bounds__(256) void combine_kernel(float4* __restrict__ out) {
    int t = blockIdx.x;
    int s0 = g_tok_slot[2 * t], s1 = g_tok_slot[2 * t + 1];
    int i = threadIdx.x;
    const float4* y0 = (const float4*)(g_y + (size_t)s0 * DMODEL) + i;
    const float4* y1 = (const float4*)(g_y + (size_t)s1 * DMODEL) + i;
    float4 a = *y0, b = *y1;
    a.x += b.x; a.y += b.y; a.z += b.z; a.w += b.w;
    out[(size_t)t * (DMODEL / 4) + i] = a;
}

// ---------------- launch ----------------
extern "C" void kernel_launch(void* const* d_in, const int* in_sizes, int n_in,
                              void* d_out, int out_size)
{
    (void)in_sizes; (void)n_in; (void)out_size;
    const float* x       = (const float*)d_in[0];
    const float* noise_u = (const float*)d_in[1];
    const float* wg      = (const float*)d_in[2];
    const float* bg      = (const float*)d_in[3];
    const float* wn      = (const float*)d_in[4];
    const float* bn      = (const float*)d_in[5];
    const float* w1      = (const float*)d_in[6];
    const float* b1      = (const float*)d_in[7];
    const float* w2      = (const float*)d_in[8];
    const float* b2      = (const float*)d_in[9];
    float* out = (float*)d_out;

    __half *w1h, *w2h;
    cudaGetSymbolAddress((void**)&w1h, g_w1h);
    cudaGetSymbolAddress((void**)&w2h, g_w2h);

    cudaFuncSetAttribute(gemm1_kernel, cudaFuncAttributeMaxDynamicSharedMemorySize, SMEM_BYTES);
    cudaFuncSetAttribute(gemm2_kernel, cudaFuncAttributeMaxDynamicSharedMemorySize, SMEM_BYTES);

    reset_kernel<<<(MAX_SLOTS + 255) / 256, 256>>>();
    router_kernel<<<T_TOK / 8, 256>>>(x, noise_u, wg, bg, wn, bn);
    offsets_kernel<<<1, 32>>>();
    scatter_kernel<<<(T_TOK * 2) / 256, 256>>>();

    // fp16 conversion pre-passes
    cvt_x_kernel<<<(int)(((size_t)T_TOK * DMODEL / 4) / 256), 256>>>((const float4*)x);
    {   // w1: [e][K=DMODEL][N=DFF] -> [e][N][K] fp16
        dim3 gdim(DFF / 32, DMODEL / 32, NEXP), bdim(32, 8);
        cvt_w_kernel<<<gdim, bdim>>>(w1, w1h, DMODEL, DFF);
    }
    {   // w2: [e][K=DFF][N=DMODEL] -> [e][N][K] fp16
        dim3 gdim(DMODEL / 32, DFF / 32, NEXP), bdim(32, 8);
        cvt_w_kernel<<<gdim, bdim>>>(w2, w2h, DFF, DMODEL);
    }

    gemm1_kernel<<<dim3(DFF / 128, MAX_TILES), NTHR, SMEM_BYTES>>>(b1);
    gemm2_kernel<<<dim3(DMODEL / 128, MAX_TILES), NTHR, SMEM_BYTES>>>(b2);
    combine_kernel<<<T_TOK, 256>>>((float4*)out);
}